// round 2
// baseline (speedup 1.0000x reference)
#include <cuda_runtime.h>
#include <math.h>

#define N_SEQ 896
#define DH    3072
#define NC    64
#define NJ    127
#define DC    1024
#define INNER 512
#define NH    8
#define HD    64

// ---------------- scratch (static device memory; no allocations) ----------------
__device__ float g_w[INNER];                       // Wo @ Wp
__device__ float g_ep[N_SEQ];                      // embeddings @ Wp
__device__ float g_bias;                           // bo @ Wp + bp
__device__ float g_wvpt[NH * DC];                  // [h][i] = Wkv_v(:,h*64+t) @ w_h
__device__ float g_vpnull[NH];
__device__ float g_lnq[(size_t)N_SEQ * DH];        // LN(embeddings)
__device__ float g_lnc[(size_t)NC * NJ * DC];      // LN(context)
__device__ float g_q[(size_t)N_SEQ * INNER];       // q projection
__device__ float g_k[(size_t)NC * NJ * INNER];     // k projection
__device__ float g_vpt[NC * NH * NJ];              // [c][h][j]

__device__ __forceinline__ float warpSum(float v) {
#pragma unroll
    for (int o = 16; o > 0; o >>= 1) v += __shfl_xor_sync(0xffffffffu, v, o);
    return v;
}
__device__ __forceinline__ float warpMax(float v) {
#pragma unroll
    for (int o = 16; o > 0; o >>= 1) v = fmaxf(v, __shfl_xor_sync(0xffffffffu, v, o));
    return v;
}

// ---------------- prep 1: dot products against Wp ----------------
// grid = 512 (w) + 896 (e_p) + 1 (bias), 256 threads
__global__ void k_prep1(const float* __restrict__ Wo, const float* __restrict__ Wp,
                        const float* __restrict__ emb, const float* __restrict__ bo,
                        const float* __restrict__ bp) {
    __shared__ float red[8];
    int bid = blockIdx.x, t = threadIdx.x;
    const float* a;
    if (bid < 512)            a = Wo  + (size_t)bid * DH;
    else if (bid < 512+N_SEQ) a = emb + (size_t)(bid - 512) * DH;
    else                      a = bo;
    float s = 0.f;
    for (int i = t; i < DH; i += 256) s = fmaf(a[i], Wp[i], s);
    s = warpSum(s);
    if ((t & 31) == 0) red[t >> 5] = s;
    __syncthreads();
    if (t == 0) {
        float S = 0.f;
#pragma unroll
        for (int i = 0; i < 8; i++) S += red[i];
        if (bid < 512)              g_w[bid] = S;
        else if (bid < 512 + N_SEQ) g_ep[bid - 512] = S;
        else                        g_bias = S + bp[0];
    }
}

// ---------------- prep 2: Wv_p^T and vp_null (needs g_w) ----------------
// grid = 33, 256 threads
__global__ void k_prep2(const float* __restrict__ Wkv, const float* __restrict__ null_v) {
    int bid = blockIdx.x, t = threadIdx.x;
    if (bid < 32) {
        int gid = bid * 256 + t;        // 0..8191
        int h = gid >> 10, i = gid & 1023;
        const float* wrow = g_w + h * HD;
        const float* src  = Wkv + (size_t)i * (2 * INNER) + INNER + h * HD;
        float s = 0.f;
#pragma unroll
        for (int d = 0; d < HD; d++) s = fmaf(src[d], wrow[d], s);
        g_wvpt[h * DC + i] = s;
    } else if (t < NH) {
        float s = 0.f;
#pragma unroll
        for (int d = 0; d < HD; d++) s = fmaf(null_v[t * HD + d], g_w[t * HD + d], s);
        g_vpnull[t] = s;
    }
}

// ---------------- LN over embeddings rows (3072) ----------------
__global__ void k_ln_q(const float* __restrict__ x, const float* __restrict__ gamma,
                       const float* __restrict__ beta) {
    __shared__ float row[DH];
    __shared__ float red[18];
    int b = blockIdx.x, t = threadIdx.x;
    const float* xr = x + (size_t)b * DH;
    float s = 0.f, ss = 0.f;
#pragma unroll
    for (int u = 0; u < 3; u++) {
        int idx = (t + u * 256) * 4;
        float4 v = *(const float4*)(xr + idx);
        row[idx] = v.x; row[idx+1] = v.y; row[idx+2] = v.z; row[idx+3] = v.w;
        s  += v.x + v.y + v.z + v.w;
        ss += v.x*v.x + v.y*v.y + v.z*v.z + v.w*v.w;
    }
    s = warpSum(s); ss = warpSum(ss);
    if ((t & 31) == 0) { red[t >> 5] = s; red[8 + (t >> 5)] = ss; }
    __syncthreads();
    if (t == 0) {
        float S = 0.f, SS = 0.f;
#pragma unroll
        for (int i = 0; i < 8; i++) { S += red[i]; SS += red[8 + i]; }
        float mu = S / DH;
        float var = SS / DH - mu * mu;
        red[16] = mu; red[17] = rsqrtf(var + 1e-5f);
    }
    __syncthreads();
    float mu = red[16], rstd = red[17];
    float* outr = g_lnq + (size_t)b * DH;
#pragma unroll
    for (int u = 0; u < 3; u++) {
        int idx = (t + u * 256) * 4;
        float4 o;
        o.x = (row[idx]   - mu) * rstd * gamma[idx]   + beta[idx];
        o.y = (row[idx+1] - mu) * rstd * gamma[idx+1] + beta[idx+1];
        o.z = (row[idx+2] - mu) * rstd * gamma[idx+2] + beta[idx+2];
        o.w = (row[idx+3] - mu) * rstd * gamma[idx+3] + beta[idx+3];
        *(float4*)(outr + idx) = o;
    }
}

// ---------------- LN over context rows (1024) + fused vp = ln @ Wv_p^T ----------------
__global__ void k_ln_c(const float* __restrict__ x, const float* __restrict__ gamma,
                       const float* __restrict__ beta) {
    __shared__ float row[DC];
    __shared__ float red[18];
    int b = blockIdx.x, t = threadIdx.x;
    const float* xr = x + (size_t)b * DC;
    int idx = t * 4;
    float4 v = *(const float4*)(xr + idx);
    float s  = v.x + v.y + v.z + v.w;
    float ss = v.x*v.x + v.y*v.y + v.z*v.z + v.w*v.w;
    s = warpSum(s); ss = warpSum(ss);
    if ((t & 31) == 0) { red[t >> 5] = s; red[8 + (t >> 5)] = ss; }
    __syncthreads();
    if (t == 0) {
        float S = 0.f, SS = 0.f;
#pragma unroll
        for (int i = 0; i < 8; i++) { S += red[i]; SS += red[8 + i]; }
        float mu = S / DC;
        float var = SS / DC - mu * mu;
        red[16] = mu; red[17] = rsqrtf(var + 1e-5f);
    }
    __syncthreads();
    float mu = red[16], rstd = red[17];
    float4 o;
    o.x = (v.x - mu) * rstd * gamma[idx]   + beta[idx];
    o.y = (v.y - mu) * rstd * gamma[idx+1] + beta[idx+1];
    o.z = (v.z - mu) * rstd * gamma[idx+2] + beta[idx+2];
    o.w = (v.w - mu) * rstd * gamma[idx+3] + beta[idx+3];
    *(float4*)(&row[idx]) = o;
    *(float4*)(g_lnc + (size_t)b * DC + idx) = o;
    __syncthreads();
    // vp: warp w handles head h = w
    int w = t >> 5, lane = t & 31;
    const float* wv = g_wvpt + w * DC;
    float acc = 0.f;
#pragma unroll
    for (int m = 0; m < 32; m++) acc = fmaf(row[lane + 32 * m], wv[lane + 32 * m], acc);
    acc = warpSum(acc);
    if (lane == 0) {
        int c = b / NJ, j = b % NJ;
        g_vpt[((size_t)c * NH + w) * NJ + j] = acc;
    }
}

// ---------------- tiled SGEMM: C[M,N] = A[M,K] @ B[K,N] (B ld = ldb) ----------------
// 64x64 tile, BK=16, 256 threads, 4x4 micro-tile. M,N,K multiples of 64/64/16.
__global__ void k_gemm(const float* __restrict__ A, const float* __restrict__ B,
                       float* __restrict__ C, int M, int N, int K, int ldb) {
    __shared__ float As[16][68];
    __shared__ float Bs[16][64];
    int t = threadIdx.x;
    int tx = t & 15, ty = t >> 4;
    int m0 = blockIdx.y * 64, n0 = blockIdx.x * 64;
    float acc[4][4];
#pragma unroll
    for (int i = 0; i < 4; i++)
#pragma unroll
        for (int j = 0; j < 4; j++) acc[i][j] = 0.f;
    int ra = t >> 2, qa = t & 3;
    int kb = t >> 4, cb = t & 15;
    for (int k0 = 0; k0 < K; k0 += 16) {
        float4 av = *(const float4*)(A + (size_t)(m0 + ra) * K + k0 + qa * 4);
        As[qa*4+0][ra] = av.x; As[qa*4+1][ra] = av.y;
        As[qa*4+2][ra] = av.z; As[qa*4+3][ra] = av.w;
        *(float4*)(&Bs[kb][cb*4]) = *(const float4*)(B + (size_t)(k0 + kb) * ldb + n0 + cb * 4);
        __syncthreads();
#pragma unroll
        for (int kk = 0; kk < 16; kk++) {
            float4 a4 = *(const float4*)(&As[kk][ty * 4]);
            float4 b4 = *(const float4*)(&Bs[kk][tx * 4]);
            float ar[4] = {a4.x, a4.y, a4.z, a4.w};
            float br[4] = {b4.x, b4.y, b4.z, b4.w};
#pragma unroll
            for (int i = 0; i < 4; i++)
#pragma unroll
                for (int j = 0; j < 4; j++) acc[i][j] = fmaf(ar[i], br[j], acc[i][j]);
        }
        __syncthreads();
    }
#pragma unroll
    for (int i = 0; i < 4; i++) {
        float4 o = make_float4(acc[i][0], acc[i][1], acc[i][2], acc[i][3]);
        *(float4*)(C + (size_t)(m0 + ty * 4 + i) * N + n0 + tx * 4) = o;
    }
}

// ---------------- attention: per (c, n-tile) block; j-per-thread, k in registers ----------------
// grid (64, 14), 128 threads (4 warps, each warp owns 32 j-slots; j=0 is null token)
__global__ void k_attn(const float* __restrict__ null_k,
                       const int* __restrict__ mask,
                       float* __restrict__ out) {
    __shared__ float q_s[64][64];
    __shared__ float mw[4][64], sw_[4][64], tw[4][64];
    __shared__ float acc_s[64];
    int c = blockIdx.x;
    int n0 = blockIdx.y * 64;
    int t = threadIdx.x;
    int w = t >> 5, lane = t & 31;
    int j = t;                                  // 0..127
    bool valid = (j == 0) || (mask[j - 1] != 0);
    if (t < 64) acc_s[t] = 0.f;

    for (int h = 0; h < NH; h++) {
        // k row for this j (registers)
        const float* kp = (j == 0) ? (null_k + h * HD)
                                   : (g_k + ((size_t)(c * NJ + (j - 1))) * INNER + h * HD);
        float kreg[64];
#pragma unroll
        for (int d4 = 0; d4 < 16; d4++) {
            float4 kv = *(const float4*)(kp + d4 * 4);
            kreg[d4*4+0] = kv.x; kreg[d4*4+1] = kv.y;
            kreg[d4*4+2] = kv.z; kreg[d4*4+3] = kv.w;
        }
        float vpj = (j == 0) ? g_vpnull[h] : g_vpt[((size_t)c * NH + h) * NJ + (j - 1)];
        // stage q tile [64 rows][64 dims] for this head
#pragma unroll
        for (int u = 0; u < 8; u++) {
            int idx = t + u * 128;
            int r = idx >> 4, c4 = idx & 15;
            *(float4*)(&q_s[r][c4 * 4]) =
                *(const float4*)(g_q + (size_t)(n0 + r) * INNER + h * HD + c4 * 4);
        }
        __syncthreads();
        for (int r = 0; r < 64; r++) {
            float sim = 0.f;
#pragma unroll
            for (int d4 = 0; d4 < 16; d4++) {
                float4 qv = *(const float4*)(&q_s[r][d4 * 4]);
                sim = fmaf(qv.x, kreg[d4*4+0], sim);
                sim = fmaf(qv.y, kreg[d4*4+1], sim);
                sim = fmaf(qv.z, kreg[d4*4+2], sim);
                sim = fmaf(qv.w, kreg[d4*4+3], sim);
            }
            sim *= 0.125f;
            if (!valid) sim = -1e30f;
            float m = warpMax(sim);
            float e = valid ? __expf(sim - m) : 0.f;
            float sacc = warpSum(e);
            float tacc = warpSum(e * vpj);
            if (lane == 0) { mw[w][r] = m; sw_[w][r] = sacc; tw[w][r] = tacc; }
        }
        __syncthreads();
        if (t < 64) {
            float m0v = mw[0][t], m1 = mw[1][t], m2 = mw[2][t], m3 = mw[3][t];
            float m = fmaxf(fmaxf(m0v, m1), fmaxf(m2, m3));
            float f0 = __expf(m0v - m), f1 = __expf(m1 - m);
            float f2 = __expf(m2 - m),  f3 = __expf(m3 - m);
            float S = sw_[0][t]*f0 + sw_[1][t]*f1 + sw_[2][t]*f2 + sw_[3][t]*f3;
            float T = tw[0][t]*f0 + tw[1][t]*f1 + tw[2][t]*f2 + tw[3][t]*f3;
            acc_s[t] += T / S;
        }
        __syncthreads();
    }
    if (t < 64) {
        int n = n0 + t;
        float x = g_ep[n] + g_bias + acc_s[t];
        float sp = fmaxf(x, 0.f) + log1pf(__expf(-fabsf(x)));   // softplus
        out[(size_t)n * NC + c] = sp;
    }
}

// ---------------- launch ----------------
extern "C" void kernel_launch(void* const* d_in, const int* in_sizes, int n_in,
                              void* d_out, int out_size) {
    const float* emb      = (const float*)d_in[0];
    const float* ctx      = (const float*)d_in[1];
    const int*   cmask    = (const int*)d_in[2];
    const float* q_gamma  = (const float*)d_in[3];
    const float* q_beta   = (const float*)d_in[4];
    const float* kv_gamma = (const float*)d_in[5];
    const float* kv_beta  = (const float*)d_in[6];
    const float* Wq       = (const float*)d_in[7];
    const float* Wkv      = (const float*)d_in[8];
    const float* null_k   = (const float*)d_in[9];
    const float* null_v   = (const float*)d_in[10];
    const float* Wo       = (const float*)d_in[11];
    const float* bo       = (const float*)d_in[12];
    const float* Wp       = (const float*)d_in[13];
    const float* bp       = (const float*)d_in[14];
    float* out = (float*)d_out;

    void *p_lnq, *p_lnc, *p_q, *p_k;
    cudaGetSymbolAddress(&p_lnq, g_lnq);
    cudaGetSymbolAddress(&p_lnc, g_lnc);
    cudaGetSymbolAddress(&p_q,   g_q);
    cudaGetSymbolAddress(&p_k,   g_k);

    k_prep1<<<512 + N_SEQ + 1, 256>>>(Wo, Wp, emb, bo, bp);
    k_prep2<<<33, 256>>>(Wkv, null_v);
    k_ln_q<<<N_SEQ, 256>>>(emb, q_gamma, q_beta);
    k_ln_c<<<NC * NJ, 256>>>(ctx, kv_gamma, kv_beta);
    // q = LN(emb) @ Wq : (896,3072)x(3072,512)
    k_gemm<<<dim3(INNER / 64, N_SEQ / 64), 256>>>((const float*)p_lnq, Wq,
                                                  (float*)p_q, N_SEQ, INNER, DH, INNER);
    // k = LN(ctx) @ Wkv[:, :512] : (8128,1024)x(1024,512), ldb = 1024
    k_gemm<<<dim3(INNER / 64, (NC * NJ) / 64), 256>>>((const float*)p_lnc, Wkv,
                                                      (float*)p_k, NC * NJ, INNER, DC, 2 * INNER);
    k_attn<<<dim3(NC, N_SEQ / 64), 128>>>(null_k, cmask, out);
}

// round 3
// speedup vs baseline: 1.0885x; 1.0885x over previous
#include <cuda_runtime.h>
#include <math.h>

#define N_SEQ 896
#define DH    3072
#define NC    64
#define NJ    127
#define DC    1024
#define INNER 512
#define NH    8
#define HD    64

// ---------------- scratch (static device memory; no allocations) ----------------
__device__ float g_w[INNER];                       // Wo @ Wp
__device__ float g_ep[N_SEQ];                      // embeddings @ Wp
__device__ float g_bias;                           // bo @ Wp + bp
__device__ float g_wvpt[NH * DC];                  // [h][i] = Wkv_v(:,h*64+t) @ w_h
__device__ float g_vpnull[NH];
__device__ float g_lnq[(size_t)N_SEQ * DH];        // LN(embeddings)
__device__ float g_lnc[(size_t)NC * NJ * DC];      // LN(context)
__device__ float g_q[(size_t)N_SEQ * INNER];       // q projection
__device__ float g_k[(size_t)NC * NJ * INNER];     // k projection
__device__ float g_vpt[NC * NH * NJ];              // [c][h][j]

__device__ __forceinline__ float warpSum(float v) {
#pragma unroll
    for (int o = 16; o > 0; o >>= 1) v += __shfl_xor_sync(0xffffffffu, v, o);
    return v;
}

// ---------------- prep 1: dot products against Wp ----------------
__global__ void k_prep1(const float* __restrict__ Wo, const float* __restrict__ Wp,
                        const float* __restrict__ emb, const float* __restrict__ bo,
                        const float* __restrict__ bp) {
    __shared__ float red[8];
    int bid = blockIdx.x, t = threadIdx.x;
    const float* a;
    if (bid < 512)            a = Wo  + (size_t)bid * DH;
    else if (bid < 512+N_SEQ) a = emb + (size_t)(bid - 512) * DH;
    else                      a = bo;
    float s = 0.f;
    for (int i = t; i < DH; i += 256) s = fmaf(a[i], Wp[i], s);
    s = warpSum(s);
    if ((t & 31) == 0) red[t >> 5] = s;
    __syncthreads();
    if (t == 0) {
        float S = 0.f;
#pragma unroll
        for (int i = 0; i < 8; i++) S += red[i];
        if (bid < 512)              g_w[bid] = S;
        else if (bid < 512 + N_SEQ) g_ep[bid - 512] = S;
        else                        g_bias = S + bp[0];
    }
}

// ---------------- prep 2: Wv_p^T and vp_null (needs g_w) ----------------
__global__ void k_prep2(const float* __restrict__ Wkv, const float* __restrict__ null_v) {
    int bid = blockIdx.x, t = threadIdx.x;
    if (bid < 32) {
        int gid = bid * 256 + t;
        int h = gid >> 10, i = gid & 1023;
        const float* wrow = g_w + h * HD;
        const float* src  = Wkv + (size_t)i * (2 * INNER) + INNER + h * HD;
        float s = 0.f;
#pragma unroll
        for (int d = 0; d < HD; d++) s = fmaf(src[d], wrow[d], s);
        g_wvpt[h * DC + i] = s;
    } else if (t < NH) {
        float s = 0.f;
#pragma unroll
        for (int d = 0; d < HD; d++) s = fmaf(null_v[t * HD + d], g_w[t * HD + d], s);
        g_vpnull[t] = s;
    }
}

// ---------------- LN over embeddings rows (3072) ----------------
__global__ void k_ln_q(const float* __restrict__ x, const float* __restrict__ gamma,
                       const float* __restrict__ beta) {
    __shared__ float row[DH];
    __shared__ float red[18];
    int b = blockIdx.x, t = threadIdx.x;
    const float* xr = x + (size_t)b * DH;
    float s = 0.f, ss = 0.f;
#pragma unroll
    for (int u = 0; u < 3; u++) {
        int idx = (t + u * 256) * 4;
        float4 v = *(const float4*)(xr + idx);
        row[idx] = v.x; row[idx+1] = v.y; row[idx+2] = v.z; row[idx+3] = v.w;
        s  += v.x + v.y + v.z + v.w;
        ss += v.x*v.x + v.y*v.y + v.z*v.z + v.w*v.w;
    }
    s = warpSum(s); ss = warpSum(ss);
    if ((t & 31) == 0) { red[t >> 5] = s; red[8 + (t >> 5)] = ss; }
    __syncthreads();
    if (t == 0) {
        float S = 0.f, SS = 0.f;
#pragma unroll
        for (int i = 0; i < 8; i++) { S += red[i]; SS += red[8 + i]; }
        float mu = S / DH;
        float var = SS / DH - mu * mu;
        red[16] = mu; red[17] = rsqrtf(var + 1e-5f);
    }
    __syncthreads();
    float mu = red[16], rstd = red[17];
    float* outr = g_lnq + (size_t)b * DH;
#pragma unroll
    for (int u = 0; u < 3; u++) {
        int idx = (t + u * 256) * 4;
        float4 o;
        o.x = (row[idx]   - mu) * rstd * gamma[idx]   + beta[idx];
        o.y = (row[idx+1] - mu) * rstd * gamma[idx+1] + beta[idx+1];
        o.z = (row[idx+2] - mu) * rstd * gamma[idx+2] + beta[idx+2];
        o.w = (row[idx+3] - mu) * rstd * gamma[idx+3] + beta[idx+3];
        *(float4*)(outr + idx) = o;
    }
}

// ---------------- LN over context rows (1024) + fused vp ----------------
__global__ void k_ln_c(const float* __restrict__ x, const float* __restrict__ gamma,
                       const float* __restrict__ beta) {
    __shared__ float row[DC];
    __shared__ float red[18];
    int b = blockIdx.x, t = threadIdx.x;
    const float* xr = x + (size_t)b * DC;
    int idx = t * 4;
    float4 v = *(const float4*)(xr + idx);
    float s  = v.x + v.y + v.z + v.w;
    float ss = v.x*v.x + v.y*v.y + v.z*v.z + v.w*v.w;
    s = warpSum(s); ss = warpSum(ss);
    if ((t & 31) == 0) { red[t >> 5] = s; red[8 + (t >> 5)] = ss; }
    __syncthreads();
    if (t == 0) {
        float S = 0.f, SS = 0.f;
#pragma unroll
        for (int i = 0; i < 8; i++) { S += red[i]; SS += red[8 + i]; }
        float mu = S / DC;
        float var = SS / DC - mu * mu;
        red[16] = mu; red[17] = rsqrtf(var + 1e-5f);
    }
    __syncthreads();
    float mu = red[16], rstd = red[17];
    float4 o;
    o.x = (v.x - mu) * rstd * gamma[idx]   + beta[idx];
    o.y = (v.y - mu) * rstd * gamma[idx+1] + beta[idx+1];
    o.z = (v.z - mu) * rstd * gamma[idx+2] + beta[idx+2];
    o.w = (v.w - mu) * rstd * gamma[idx+3] + beta[idx+3];
    *(float4*)(&row[idx]) = o;
    *(float4*)(g_lnc + (size_t)b * DC + idx) = o;
    __syncthreads();
    int w = t >> 5, lane = t & 31;
    const float* wv = g_wvpt + w * DC;
    float acc = 0.f;
#pragma unroll
    for (int m = 0; m < 32; m++) acc = fmaf(row[lane + 32 * m], wv[lane + 32 * m], acc);
    acc = warpSum(acc);
    if (lane == 0) {
        int c = b / NJ, j = b % NJ;
        g_vpt[((size_t)c * NH + w) * NJ + j] = acc;
    }
}

// ---------------- fused SGEMM: q-proj + k-proj in one grid ----------------
// Tile 64(M) x 128(N), BK=16, 256 threads, 4x8 microtile, register prefetch.
// blocks [0,508): k GEMM (M=8128,K=1024); blocks [508,564): q GEMM (M=896,K=3072)
__global__ void k_gemm_fused(const float* __restrict__ Wq, const float* __restrict__ Wkv) {
    __shared__ float As[16][68];
    __shared__ float Bs[16][128];
    int t = threadIdx.x, bid = blockIdx.x;
    const float *A, *B; float *C; int lda, ldb, K;
    int bm, bn;
    if (bid < 508) {
        bm = bid >> 2; bn = bid & 3;
        A = g_lnc; lda = DC; K = DC; B = Wkv; ldb = 2 * INNER; C = g_k;
    } else {
        int l = bid - 508; bm = l >> 2; bn = l & 3;
        A = g_lnq; lda = DH; K = DH; B = Wq; ldb = INNER; C = g_q;
    }
    int m0 = bm * 64, n0 = bn * 128;
    int tx = t & 15, ty = t >> 4;
    int ra = t >> 2, qa = t & 3;          // A loader: row ra, k-chunk qa*4
    int kb = t >> 4, cb = t & 15;         // B loader: k-row kb, col cb*8
    float acc[4][8];
#pragma unroll
    for (int i = 0; i < 4; i++)
#pragma unroll
        for (int j = 0; j < 8; j++) acc[i][j] = 0.f;

    const float* Aip = A + (size_t)(m0 + ra) * lda + qa * 4;
    const float* Bip = B + (size_t)kb * ldb + n0 + cb * 8;
    float4 ap  = *(const float4*)Aip;
    float4 bp0 = *(const float4*)Bip;
    float4 bp1 = *(const float4*)(Bip + 4);

    for (int k0 = 0; k0 < K; k0 += 16) {
        As[qa*4+0][ra] = ap.x; As[qa*4+1][ra] = ap.y;
        As[qa*4+2][ra] = ap.z; As[qa*4+3][ra] = ap.w;
        *(float4*)(&Bs[kb][cb*8])     = bp0;
        *(float4*)(&Bs[kb][cb*8 + 4]) = bp1;
        __syncthreads();
        if (k0 + 16 < K) {
            ap  = *(const float4*)(Aip + k0 + 16);
            bp0 = *(const float4*)(Bip + (size_t)(k0 + 16) * ldb);
            bp1 = *(const float4*)(Bip + (size_t)(k0 + 16) * ldb + 4);
        }
#pragma unroll
        for (int kk = 0; kk < 16; kk++) {
            float4 a4 = *(const float4*)(&As[kk][ty * 4]);
            float4 b0 = *(const float4*)(&Bs[kk][tx * 8]);
            float4 b1 = *(const float4*)(&Bs[kk][tx * 8 + 4]);
            float ar[4] = {a4.x, a4.y, a4.z, a4.w};
            float br[8] = {b0.x, b0.y, b0.z, b0.w, b1.x, b1.y, b1.z, b1.w};
#pragma unroll
            for (int i = 0; i < 4; i++)
#pragma unroll
                for (int j = 0; j < 8; j++) acc[i][j] = fmaf(ar[i], br[j], acc[i][j]);
        }
        __syncthreads();
    }
#pragma unroll
    for (int i = 0; i < 4; i++) {
        float4 o0 = make_float4(acc[i][0], acc[i][1], acc[i][2], acc[i][3]);
        float4 o1 = make_float4(acc[i][4], acc[i][5], acc[i][6], acc[i][7]);
        float* cp = C + (size_t)(m0 + ty * 4 + i) * INNER + n0 + tx * 8;
        *(float4*)cp = o0; *(float4*)(cp + 4) = o1;
    }
}

// ---------------- attention as GEMM: sim[64r][128j] = Q(64x64) @ K^T per (c,h) ----------------
// grid (64, 14), 256 threads (16x16), 4x8 microtile. Dynamic smem.
__global__ void k_attn(const float* __restrict__ null_k, const int* __restrict__ mask,
                       float* __restrict__ out) {
    extern __shared__ float sm[];
    float (*Qs)[68]   = (float(*)[68])sm;                        // 64 x 68
    float (*Ks)[128]  = (float(*)[128])(sm + 64 * 68);           // 64 x 128
    float* vps        = sm + 64 * 68 + 64 * 128;                 // 128
    float* validS     = vps + 128;                               // 128
    float (*RedA)[17] = (float(*)[17])(validS + 128);            // 64 x 17
    float (*RedB)[17] = (float(*)[17])(validS + 128 + 64 * 17);  // 64 x 17
    float* rowmaxS    = validS + 128 + 2 * 64 * 17;              // 64
    float* rowacc     = rowmaxS + 64;                            // 64

    int c = blockIdx.x, n0 = blockIdx.y * 64;
    int t = threadIdx.x;
    int tx = t & 15, ty = t >> 4;

    if (t < 128) validS[t] = (t == 0 || mask[t - 1] != 0) ? 1.f : 0.f;
    if (t < 64)  rowacc[t] = 0.f;
    __syncthreads();

    float vj[8];
#pragma unroll
    for (int jj = 0; jj < 8; jj++) vj[jj] = validS[tx * 8 + jj];

    int rq = t >> 2, dq0 = (t & 3) * 4;     // Q loader
    int jk = t >> 1, dk0 = (t & 1) * 32;    // K loader
    const float* kp = (jk == 0) ? null_k
                                : g_k + ((size_t)(c * NJ + jk - 1)) * INNER;

    for (int h = 0; h < NH; h++) {
        // stage Q^T: Qs[d][r]
#pragma unroll
        for (int u = 0; u < 4; u++) {
            int d = dq0 + u * 16;
            float4 qv = *(const float4*)(g_q + (size_t)(n0 + rq) * INNER + h * HD + d);
            Qs[d][rq] = qv.x; Qs[d+1][rq] = qv.y; Qs[d+2][rq] = qv.z; Qs[d+3][rq] = qv.w;
        }
        // stage K^T: Ks[d][j]
#pragma unroll
        for (int u = 0; u < 8; u++) {
            int d = dk0 + u * 4;
            float4 kv = *(const float4*)(kp + h * HD + d);
            Ks[d][jk] = kv.x; Ks[d+1][jk] = kv.y; Ks[d+2][jk] = kv.z; Ks[d+3][jk] = kv.w;
        }
        if (t < 128)
            vps[t] = (t == 0) ? g_vpnull[h] : g_vpt[((size_t)c * NH + h) * NJ + t - 1];
        __syncthreads();

        float acc[4][8];
#pragma unroll
        for (int i = 0; i < 4; i++)
#pragma unroll
            for (int jj = 0; jj < 8; jj++) acc[i][jj] = 0.f;
#pragma unroll 8
        for (int kk = 0; kk < 64; kk++) {
            float4 a4 = *(const float4*)(&Qs[kk][ty * 4]);
            float4 b0 = *(const float4*)(&Ks[kk][tx * 8]);
            float4 b1 = *(const float4*)(&Ks[kk][tx * 8 + 4]);
            float ar[4] = {a4.x, a4.y, a4.z, a4.w};
            float br[8] = {b0.x, b0.y, b0.z, b0.w, b1.x, b1.y, b1.z, b1.w};
#pragma unroll
            for (int i = 0; i < 4; i++)
#pragma unroll
                for (int jj = 0; jj < 8; jj++) acc[i][jj] = fmaf(ar[i], br[jj], acc[i][jj]);
        }

        float vpr[8];
#pragma unroll
        for (int jj = 0; jj < 8; jj++) vpr[jj] = vps[tx * 8 + jj];

        // local max over this thread's 8 j (valid only)
#pragma unroll
        for (int i = 0; i < 4; i++) {
            float m = -1e30f;
#pragma unroll
            for (int jj = 0; jj < 8; jj++) {
                acc[i][jj] *= 0.125f;
                if (vj[jj] > 0.f) m = fmaxf(m, acc[i][jj]);
            }
            RedA[ty * 4 + i][tx] = m;
        }
        __syncthreads();
        if (t < 64) {
            float m = RedA[t][0];
#pragma unroll
            for (int k = 1; k < 16; k++) m = fmaxf(m, RedA[t][k]);
            rowmaxS[t] = m;
        }
        __syncthreads();
#pragma unroll
        for (int i = 0; i < 4; i++) {
            int r = ty * 4 + i;
            float rm = rowmaxS[r];
            float s = 0.f, tv = 0.f;
#pragma unroll
            for (int jj = 0; jj < 8; jj++) {
                float e = vj[jj] * __expf(acc[i][jj] - rm);
                s += e; tv += e * vpr[jj];
            }
            RedA[r][tx] = s; RedB[r][tx] = tv;
        }
        __syncthreads();
        if (t < 64) {
            float S = 0.f, T = 0.f;
#pragma unroll
            for (int k = 0; k < 16; k++) { S += RedA[t][k]; T += RedB[t][k]; }
            rowacc[t] += T / S;
        }
        __syncthreads();
    }
    if (t < 64) {
        int n = n0 + t;
        float x = g_ep[n] + g_bias + rowacc[t];
        out[(size_t)n * NC + c] = fmaxf(x, 0.f) + log1pf(__expf(-fabsf(x)));
    }
}

// ---------------- launch ----------------
extern "C" void kernel_launch(void* const* d_in, const int* in_sizes, int n_in,
                              void* d_out, int out_size) {
    const float* emb      = (const float*)d_in[0];
    const float* ctx      = (const float*)d_in[1];
    const int*   cmask    = (const int*)d_in[2];
    const float* q_gamma  = (const float*)d_in[3];
    const float* q_beta   = (const float*)d_in[4];
    const float* kv_gamma = (const float*)d_in[5];
    const float* kv_beta  = (const float*)d_in[6];
    const float* Wq       = (const float*)d_in[7];
    const float* Wkv      = (const float*)d_in[8];
    const float* null_k   = (const float*)d_in[9];
    const float* null_v   = (const float*)d_in[10];
    const float* Wo       = (const float*)d_in[11];
    const float* bo       = (const float*)d_in[12];
    const float* Wp       = (const float*)d_in[13];
    const float* bp       = (const float*)d_in[14];
    float* out = (float*)d_out;

    // attn dynamic smem: Qs + Ks + vps + valid + RedA + RedB + rowmax + rowacc
    const int attn_smem = (64*68 + 64*128 + 128 + 128 + 2*64*17 + 64 + 64) * (int)sizeof(float);
    cudaFuncSetAttribute(k_attn, cudaFuncAttributeMaxDynamicSharedMemorySize, attn_smem);

    k_prep1<<<512 + N_SEQ + 1, 256>>>(Wo, Wp, emb, bo, bp);
    k_prep2<<<33, 256>>>(Wkv, null_v);
    k_ln_q<<<N_SEQ, 256>>>(emb, q_gamma, q_beta);
    k_ln_c<<<NC * NJ, 256>>>(ctx, kv_gamma, kv_beta);
    k_gemm_fused<<<508 + 56, 256>>>(Wq, Wkv);
    k_attn<<<dim3(NC, N_SEQ / 64), 256, attn_smem>>>(null_k, cmask, out);
}